// round 10
// baseline (speedup 1.0000x reference)
#include <cuda_runtime.h>
#include <cuda_bf16.h>
#include <math.h>
#include <stdint.h>

#define BATCH 2
#define S_LEN 2048
#define D_MODEL 1024
#define NHEAD 16
#define DHEAD 64
#define NEGBIG -1e30f

// fp32 scratch
__device__ float g_q[BATCH*NHEAD*S_LEN*DHEAD];
__device__ float g_k[BATCH*NHEAD*S_LEN*DHEAD];
__device__ float g_v[BATCH*NHEAD*S_LEN*DHEAD];

// bf16 hi/lo planes
__device__ __nv_bfloat16 g_xh[4096*1024],  g_xl[4096*1024];
__device__ __nv_bfloat16 g_ath[4096*1024], g_atl[4096*1024];   // attention out planes
__device__ __nv_bfloat16 g_wqh[3072*1024], g_wql[3072*1024];   // transposed N x K
__device__ __nv_bfloat16 g_woh[1024*1024], g_wol[1024*1024];   // transposed N x K

__device__ __forceinline__ void bf16split(float x, __nv_bfloat16& hi, __nv_bfloat16& lo) {
    hi = __float2bfloat16_rn(x);
    lo = __float2bfloat16_rn(x - __bfloat162float(hi));
}

// ---------------------------------------------------------------------------
// Pre-pass 1: elementwise split
// ---------------------------------------------------------------------------
__global__ void split_plain_kernel(const float* __restrict__ in,
                                   __nv_bfloat16* __restrict__ hi,
                                   __nv_bfloat16* __restrict__ lo)
{
    int i = (blockIdx.x * 256 + threadIdx.x) * 4;
    float4 v = *reinterpret_cast<const float4*>(in + i);
    __nv_bfloat16 h0,l0,h1,l1,h2,l2,h3,l3;
    bf16split(v.x,h0,l0); bf16split(v.y,h1,l1);
    bf16split(v.z,h2,l2); bf16split(v.w,h3,l3);
    *reinterpret_cast<__nv_bfloat162*>(hi + i)     = __nv_bfloat162(h0,h1);
    *reinterpret_cast<__nv_bfloat162*>(hi + i + 2) = __nv_bfloat162(h2,h3);
    *reinterpret_cast<__nv_bfloat162*>(lo + i)     = __nv_bfloat162(l0,l1);
    *reinterpret_cast<__nv_bfloat162*>(lo + i + 2) = __nv_bfloat162(l2,l3);
}

// ---------------------------------------------------------------------------
// Pre-pass 2: split + transpose
// ---------------------------------------------------------------------------
__global__ void transpose_split_kernel(const float* __restrict__ in,
                                       __nv_bfloat16* __restrict__ hiT,
                                       __nv_bfloat16* __restrict__ loT,
                                       int R, int C)
{
    __shared__ float t[32][33];
    const int tx = threadIdx.x, ty = threadIdx.y;
    const int r0 = blockIdx.y * 32, c0 = blockIdx.x * 32;
    #pragma unroll
    for (int i = 0; i < 4; i++)
        t[ty + i*8][tx] = in[(long)(r0 + ty + i*8) * C + c0 + tx];
    __syncthreads();
    #pragma unroll
    for (int i = 0; i < 4; i++) {
        float v = t[tx][ty + i*8];
        __nv_bfloat16 h, l;
        bf16split(v, h, l);
        long o = (long)(c0 + ty + i*8) * R + r0 + tx;
        hiT[o] = h; loT[o] = l;
    }
}

// ---------------------------------------------------------------------------
// GEMM (unchanged from R8): CTA 128x128, 4 warps, 64x64 warp tiles.
// ---------------------------------------------------------------------------
#define KP 40
#define GPLANE (128*KP)
#define GEMM_SMEM_BYTES (8 * GPLANE * (int)sizeof(__nv_bfloat16))

__device__ __forceinline__ void cpasync16(__nv_bfloat16* smem, const __nv_bfloat16* g) {
    uint32_t s = (uint32_t)__cvta_generic_to_shared(smem);
    asm volatile("cp.async.cg.shared.global [%0], [%1], 16;\n" :: "r"(s), "l"(g));
}

__device__ __forceinline__ void mma_bf16(float* c, const uint32_t* a, const uint32_t* b) {
    asm volatile(
        "mma.sync.aligned.m16n8k16.row.col.f32.bf16.bf16.f32 "
        "{%0,%1,%2,%3}, {%4,%5,%6,%7}, {%8,%9}, {%0,%1,%2,%3};"
        : "+f"(c[0]), "+f"(c[1]), "+f"(c[2]), "+f"(c[3])
        : "r"(a[0]), "r"(a[1]), "r"(a[2]), "r"(a[3]), "r"(b[0]), "r"(b[1]));
}

__device__ __forceinline__ void ldsm_x4(uint32_t* r, uint32_t addr) {
    asm volatile("ldmatrix.sync.aligned.m8n8.x4.shared.b16 {%0,%1,%2,%3}, [%4];"
                 : "=r"(r[0]), "=r"(r[1]), "=r"(r[2]), "=r"(r[3]) : "r"(addr));
}

template<int N, bool IS_QKV>
__global__ __launch_bounds__(128, 2)
void bf16_gemm_kernel(const __nv_bfloat16* __restrict__ Ahg,
                      const __nv_bfloat16* __restrict__ Alg,
                      const __nv_bfloat16* __restrict__ Bhg,
                      const __nv_bfloat16* __restrict__ Blg,
                      float* __restrict__ Out)
{
    extern __shared__ __nv_bfloat16 smg[];
    __nv_bfloat16* Ah = smg;
    __nv_bfloat16* Al = smg + 2*GPLANE;
    __nv_bfloat16* Bh = smg + 4*GPLANE;
    __nv_bfloat16* Bl = smg + 6*GPLANE;

    const int K = 1024;
    const int tid  = threadIdx.x;
    const int lane = tid & 31;
    const int wid  = tid >> 5;
    const int wm   = wid & 1;
    const int wn   = wid >> 1;
    const int m0 = blockIdx.y * 128;
    const int n0 = blockIdx.x * 128;

    const int lrow = ((lane >> 3) & 1) * 8 + (lane & 7);
    const int lkq  = (lane >> 4) * 8;
    const uint32_t lmo = (uint32_t)((lrow * KP + lkq) * 2);

    const uint32_t sAh = (uint32_t)__cvta_generic_to_shared(Ah);
    const uint32_t sAl = sAh + 2*GPLANE*2;
    const uint32_t sBh = sAh + 4*GPLANE*2;
    const uint32_t sBl = sAh + 6*GPLANE*2;

    float acc[4][8][4];
    #pragma unroll
    for (int mt = 0; mt < 4; mt++)
        #pragma unroll
        for (int nt = 0; nt < 8; nt++)
            #pragma unroll
            for (int i = 0; i < 4; i++) acc[mt][nt][i] = 0.f;

    auto load_tiles = [&](int k0, int buf) {
        #pragma unroll
        for (int u = 0; u < 4; u++) {
            int c = tid + u*128;
            int row = c >> 2, kc = (c & 3) * 8;
            long go = (long)(m0 + row)*K + k0 + kc;
            cpasync16(&Ah[buf*GPLANE + row*KP + kc], Ahg + go);
            cpasync16(&Al[buf*GPLANE + row*KP + kc], Alg + go);
        }
        #pragma unroll
        for (int u = 0; u < 4; u++) {
            int c = tid + u*128;
            int row = c >> 2, kc = (c & 3) * 8;
            long go = (long)(n0 + row)*K + k0 + kc;
            cpasync16(&Bh[buf*GPLANE + row*KP + kc], Bhg + go);
            cpasync16(&Bl[buf*GPLANE + row*KP + kc], Blg + go);
        }
        asm volatile("cp.async.commit_group;\n");
    };

    load_tiles(0, 0);

    const int NIT = K / 32;
    for (int it = 0; it < NIT; ++it) {
        const int buf = it & 1;
        asm volatile("cp.async.wait_group 0;\n");
        __syncthreads();
        if (it + 1 < NIT) load_tiles((it+1)*32, buf ^ 1);

        const uint32_t bofs = (uint32_t)(buf*GPLANE*2);

        #pragma unroll
        for (int ks = 0; ks < 2; ks++) {
            const uint32_t kbo = bofs + (uint32_t)(ks*16*2) + lmo;

            uint32_t ahf[4][4], alf[4][4];
            #pragma unroll
            for (int mt = 0; mt < 4; mt++) {
                uint32_t ro = (uint32_t)((wm*64 + mt*16) * KP * 2);
                ldsm_x4(ahf[mt], sAh + ro + kbo);
                ldsm_x4(alf[mt], sAl + ro + kbo);
            }
            uint32_t bhf[8][2], blf[8][2];
            #pragma unroll
            for (int p = 0; p < 4; p++) {
                uint32_t ro = (uint32_t)((wn*64 + p*16) * KP * 2);
                uint32_t r[4];
                ldsm_x4(r, sBh + ro + kbo);
                bhf[2*p+0][0] = r[0]; bhf[2*p+1][0] = r[1];
                bhf[2*p+0][1] = r[2]; bhf[2*p+1][1] = r[3];
                ldsm_x4(r, sBl + ro + kbo);
                blf[2*p+0][0] = r[0]; blf[2*p+1][0] = r[1];
                blf[2*p+0][1] = r[2]; blf[2*p+1][1] = r[3];
            }
            #pragma unroll
            for (int mt = 0; mt < 4; mt++)
                #pragma unroll
                for (int nt = 0; nt < 8; nt++) {
                    mma_bf16(acc[mt][nt], ahf[mt], blf[nt]);
                    mma_bf16(acc[mt][nt], alf[mt], bhf[nt]);
                    mma_bf16(acc[mt][nt], ahf[mt], bhf[nt]);
                }
        }
        __syncthreads();
    }

    #pragma unroll
    for (int mt = 0; mt < 4; mt++) {
        #pragma unroll
        for (int i = 0; i < 2; i++) {
            int row = m0 + wm*64 + mt*16 + (lane >> 2) + i*8;
            #pragma unroll
            for (int nt = 0; nt < 8; nt++) {
                int col = n0 + wn*64 + nt*8 + (lane & 3)*2;
                float2 v = make_float2(acc[mt][nt][i*2+0], acc[mt][nt][i*2+1]);
                if (IS_QKV) {
                    int b = row >> 11, s = row & 2047;
                    int which = col >> 10;
                    int h = (col >> 6) & 15;
                    int dh = col & 63;
                    float* dst = (which == 0) ? g_q : (which == 1) ? g_k : g_v;
                    *reinterpret_cast<float2*>(
                        &dst[(((long)(b*NHEAD + h))*S_LEN + s)*DHEAD + dh]) = v;
                } else {
                    *reinterpret_cast<float2*>(&Out[(long)row*N + col]) = v;
                }
            }
        }
    }
}

// ---------------------------------------------------------------------------
// Tensor-core banded attention. 128 thr (4 warps), warp = 16 q-rows x 192 keys.
// QK^T and PV via 3-term bf16 split mma. P repacked from S regs (FA2 trick).
// smem planes: Qh/Ql [64][72], Kh/Kl [192][72], Vh/Vl(transposed) [64][200].
// ---------------------------------------------------------------------------
#define QP_ 72
#define KPP 72
#define VP_ 200
#define AQ_OFF 0
#define AQL_OFF (64*QP_)
#define AK_OFF (2*64*QP_)
#define AKL_OFF (AK_OFF + 192*KPP)
#define AV_OFF (AK_OFF + 2*192*KPP)
#define AVL_OFF (AV_OFF + 64*VP_)
#define ATT_SMEM_ELEMS (AV_OFF + 2*64*VP_)
#define ATT_SMEM_BYTES (ATT_SMEM_ELEMS * 2)

__device__ __forceinline__ uint32_t packbf(float a, float b) {
    __nv_bfloat162 v(__float2bfloat16_rn(a), __float2bfloat16_rn(b));
    return *reinterpret_cast<uint32_t*>(&v);
}
__device__ __forceinline__ uint32_t packlo(float a, float b, uint32_t hi) {
    __nv_bfloat162 h = *reinterpret_cast<__nv_bfloat162*>(&hi);
    __nv_bfloat162 v(__float2bfloat16_rn(a - __bfloat162float(h.x)),
                     __float2bfloat16_rn(b - __bfloat162float(h.y)));
    return *reinterpret_cast<uint32_t*>(&v);
}

__global__ __launch_bounds__(128, 1)
void attn_kernel(const float* __restrict__ bias)
{
    extern __shared__ __nv_bfloat16 smb[];
    const int tid = threadIdx.x;
    const int lane = tid & 31;
    const int wid = tid >> 5;
    const int qt = blockIdx.x;
    const int bh = blockIdx.y;
    const int qstart = qt * 64;
    const int jbase = qstart - 128;

    const float* qg = g_q + (long)bh * S_LEN * DHEAD;
    const float* kg = g_k + (long)bh * S_LEN * DHEAD;
    const float* vg = g_v + (long)bh * S_LEN * DHEAD;

    // ---- stage split planes ----
    for (int t = tid; t < 64*64; t += 128) {
        int s = t >> 6, dh = t & 63;
        __nv_bfloat16 h, l;
        bf16split(qg[(long)(qstart + s)*DHEAD + dh], h, l);
        smb[AQ_OFF + s*QP_ + dh] = h;
        smb[AQL_OFF + s*QP_ + dh] = l;
    }
    for (int t = tid; t < 192*64; t += 128) {
        int r = t >> 6, dh = t & 63;
        int j = jbase + r;
        float kv = (j >= 0) ? kg[(long)j*DHEAD + dh] : 0.f;
        float vv = (j >= 0) ? vg[(long)j*DHEAD + dh] : 0.f;
        __nv_bfloat16 h, l;
        bf16split(kv, h, l);
        smb[AK_OFF + r*KPP + dh] = h;
        smb[AKL_OFF + r*KPP + dh] = l;
        bf16split(vv, h, l);
        smb[AV_OFF + dh*VP_ + r] = h;     // transposed
        smb[AVL_OFF + dh*VP_ + r] = l;
    }
    __syncthreads();

    const uint32_t sb = (uint32_t)__cvta_generic_to_shared(smb);
    const int lrow = ((lane >> 3) & 1) * 8 + (lane & 7);
    const int lkq  = (lane >> 4) * 8;
    const uint32_t lmoQ = (uint32_t)((lrow * QP_ + lkq) * 2);
    const uint32_t lmoK = (uint32_t)((lrow * KPP + lkq) * 2);
    const uint32_t lmoV = (uint32_t)((lrow * VP_ + lkq) * 2);

    // ---- QK^T: S (16 x 192 per warp) ----
    float S[24][4];
    #pragma unroll
    for (int nt = 0; nt < 24; nt++)
        #pragma unroll
        for (int i = 0; i < 4; i++) S[nt][i] = 0.f;

    #pragma unroll
    for (int ks = 0; ks < 4; ks++) {
        const uint32_t kb = (uint32_t)(ks*16*2);
        uint32_t qh[4], ql[4];
        ldsm_x4(qh, sb + (uint32_t)(AQ_OFF*2)  + (uint32_t)(wid*16*QP_*2) + kb + lmoQ);
        ldsm_x4(ql, sb + (uint32_t)(AQL_OFF*2) + (uint32_t)(wid*16*QP_*2) + kb + lmoQ);
        #pragma unroll
        for (int p = 0; p < 12; p++) {
            uint32_t r[4], bhh[2][2], bll[2][2];
            ldsm_x4(r, sb + (uint32_t)(AK_OFF*2) + (uint32_t)(p*16*KPP*2) + kb + lmoK);
            bhh[0][0]=r[0]; bhh[1][0]=r[1]; bhh[0][1]=r[2]; bhh[1][1]=r[3];
            ldsm_x4(r, sb + (uint32_t)(AKL_OFF*2) + (uint32_t)(p*16*KPP*2) + kb + lmoK);
            bll[0][0]=r[0]; bll[1][0]=r[1]; bll[0][1]=r[2]; bll[1][1]=r[3];
            #pragma unroll
            for (int q2 = 0; q2 < 2; q2++) {
                mma_bf16(S[2*p+q2], qh, bll[q2]);
                mma_bf16(S[2*p+q2], ql, bhh[q2]);
                mma_bf16(S[2*p+q2], qh, bhh[q2]);
            }
        }
    }

    // ---- bias + masks + softmax (in registers) ----
    const int row0 = wid*16 + (lane >> 2);
    const int gi0 = qstart + row0;
    const int gi1 = gi0 + 8;
    const float* bb = bias + (long)bh * S_LEN * S_LEN;
    const float scale = 0.125f;

    float m0 = NEGBIG, m1 = NEGBIG;
    #pragma unroll
    for (int nt = 0; nt < 24; nt++) {
        int cj = nt*8 + (lane & 3)*2;
        int gj = jbase + cj;
        int cg = (gj >= 0) ? gj : 0;
        float2 b0 = *reinterpret_cast<const float2*>(&bb[(long)gi0*S_LEN + cg]);
        float2 b1 = *reinterpret_cast<const float2*>(&bb[(long)gi1*S_LEN + cg]);
        bool v00 = (gj >= 0)   && (gj   <= gi0) && (gi0 - gj   <= 128);
        bool v01 = (gj+1 >= 0) && (gj+1 <= gi0) && (gi0 - gj-1 <= 128);
        bool v10 = (gj >= 0)   && (gj   <= gi1) && (gi1 - gj   <= 128);
        bool v11 = (gj+1 >= 0) && (gj+1 <= gi1) && (gi1 - gj-1 <= 128);
        S[nt][0] = v00 ? S[nt][0]*scale + b0.x : NEGBIG;
        S[nt][1] = v01 ? S[nt][1]*scale + b0.y : NEGBIG;
        S[nt][2] = v10 ? S[nt][2]*scale + b1.x : NEGBIG;
        S[nt][3] = v11 ? S[nt][3]*scale + b1.y : NEGBIG;
        m0 = fmaxf(m0, fmaxf(S[nt][0], S[nt][1]));
        m1 = fmaxf(m1, fmaxf(S[nt][2], S[nt][3]));
    }
    #pragma unroll
    for (int o = 1; o <= 2; o <<= 1) {
        m0 = fmaxf(m0, __shfl_xor_sync(0xffffffffu, m0, o));
        m1 = fmaxf(m1, __shfl_xor_sync(0xffffffffu, m1, o));
    }
    float s0 = 0.f, s1 = 0.f;
    #pragma unroll
    for (int nt = 0; nt < 24; nt++) {
        S[nt][0] = __expf(S[nt][0] - m0);
        S[nt][1] = __expf(S[nt][1] - m0);
        S[nt][2] = __expf(S[nt][2] - m1);
        S[nt][3] = __expf(S[nt][3] - m1);
        s0 += S[nt][0] + S[nt][1];
        s1 += S[nt][2] + S[nt][3];
    }
    #pragma unroll
    for (int o = 1; o <= 2; o <<= 1) {
        s0 += __shfl_xor_sync(0xffffffffu, s0, o);
        s1 += __shfl_xor_sync(0xffffffffu, s1, o);
    }
    const float i0 = 1.f / s0, i1 = 1.f / s1;
    #pragma unroll
    for (int nt = 0; nt < 24; nt++) {
        S[nt][0] *= i0; S[nt][1] *= i0;
        S[nt][2] *= i1; S[nt][3] *= i1;
    }

    // ---- PV: O (16 x 64 per warp), P from S regs ----
    float O[8][4];
    #pragma unroll
    for (int nt = 0; nt < 8; nt++)
        #pragma unroll
        for (int i = 0; i < 4; i++) O[nt][i] = 0.f;

    #pragma unroll
    for (int ks = 0; ks < 12; ks++) {
        uint32_t ah[4], al[4];
        ah[0] = packbf(S[2*ks][0],   S[2*ks][1]);
        ah[1] = packbf(S[2*ks][2],   S[2*ks][3]);
        ah[2] = packbf(S[2*ks+1][0], S[2*ks+1][1]);
        ah[3] = packbf(S[2*ks+1][2], S[2*ks+1][3]);
        al[0] = packlo(S[2*ks][0],   S[2*ks][1],   ah[0]);
        al[1] = packlo(S[2*ks][2],   S[2*ks][3],   ah[1]);
        al[2] = packlo(S[2*ks+1][0], S[2*ks+1][1], ah[2]);
        al[3] = packlo(S[2*ks+1][2], S[2*ks+1][3], ah[3]);

        const uint32_t kb = (uint32_t)(ks*16*2);
        #pragma unroll
        for (int p = 0; p < 4; p++) {
            uint32_t r[4], bhh[2][2], bll[2][2];
            ldsm_x4(r, sb + (uint32_t)(AV_OFF*2) + (uint32_t)(p*16*VP_*2) + kb + lmoV);
            bhh[0][0]=r[0]; bhh[1][0]=r[1]; bhh[0][1]=r[2]; bhh[1][1]=r[3];
            ldsm_x4(r, sb + (uint32_t)(AVL_OFF*2) + (uint32_t)(p*16*VP_*2) + kb + lmoV);
            bll[0][0]=r[0]; bll[1][0]=r[1]; bll[0][1]=r[2]; bll[1][1]=r[3];
            #pragma unroll
            for (int q2 = 0; q2 < 2; q2++) {
                mma_bf16(O[2*p+q2], ah, bll[q2]);
                mma_bf16(O[2*p+q2], al, bhh[q2]);
                mma_bf16(O[2*p+q2], ah, bhh[q2]);
            }
        }
    }

    // ---- epilogue: write bf16 hi/lo planes of attention output ----
    const int b = bh >> 4, h = bh & 15;
    #pragma unroll
    for (int nt = 0; nt < 8; nt++) {
        int col = nt*8 + (lane & 3)*2;
        long o0 = ((long)(b*S_LEN + gi0))*D_MODEL + h*DHEAD + col;
        long o1 = ((long)(b*S_LEN + gi1))*D_MODEL + h*DHEAD + col;
        uint32_t h0 = packbf(O[nt][0], O[nt][1]);
        uint32_t l0 = packlo(O[nt][0], O[nt][1], h0);
        uint32_t h1 = packbf(O[nt][2], O[nt][3]);
        uint32_t l1 = packlo(O[nt][2], O[nt][3], h1);
        *reinterpret_cast<uint32_t*>(&g_ath[o0]) = h0;
        *reinterpret_cast<uint32_t*>(&g_atl[o0]) = l0;
        *reinterpret_cast<uint32_t*>(&g_ath[o1]) = h1;
        *reinterpret_cast<uint32_t*>(&g_atl[o1]) = l1;
    }
}

// ---------------------------------------------------------------------------
extern "C" void kernel_launch(void* const* d_in, const int* in_sizes, int n_in,
                              void* d_out, int out_size)
{
    const float* x    = (const float*)d_in[0];
    const float* bias = (const float*)d_in[1];
    // d_in[2] = causal mask (recomputed analytically in-kernel)
    const float* Wqkv = (const float*)d_in[3];
    const float* Wout = (const float*)d_in[4];
    float* out = (float*)d_out;

    __nv_bfloat16 *xh, *xl, *ath, *atl, *wqh, *wql, *woh, *wol;
    cudaGetSymbolAddress((void**)&xh,  g_xh);  cudaGetSymbolAddress((void**)&xl,  g_xl);
    cudaGetSymbolAddress((void**)&ath, g_ath); cudaGetSymbolAddress((void**)&atl, g_atl);
    cudaGetSymbolAddress((void**)&wqh, g_wqh); cudaGetSymbolAddress((void**)&wql, g_wql);
    cudaGetSymbolAddress((void**)&woh, g_woh); cudaGetSymbolAddress((void**)&wol, g_wol);

    cudaFuncSetAttribute(bf16_gemm_kernel<3072, true>,
                         cudaFuncAttributeMaxDynamicSharedMemorySize, GEMM_SMEM_BYTES);
    cudaFuncSetAttribute(bf16_gemm_kernel<1024, false>,
                         cudaFuncAttributeMaxDynamicSharedMemorySize, GEMM_SMEM_BYTES);
    cudaFuncSetAttribute(attn_kernel,
                         cudaFuncAttributeMaxDynamicSharedMemorySize, ATT_SMEM_BYTES);

    // Pre-passes
    split_plain_kernel<<<4096, 256>>>(x, xh, xl);
    transpose_split_kernel<<<dim3(3072/32, 1024/32), dim3(32, 8)>>>(Wqkv, wqh, wql, 1024, 3072);
    transpose_split_kernel<<<dim3(1024/32, 1024/32), dim3(32, 8)>>>(Wout, woh, wol, 1024, 1024);

    // QKV projection
    bf16_gemm_kernel<3072, true><<<dim3(24, 32), 128, GEMM_SMEM_BYTES>>>(
        xh, xl, wqh, wql, nullptr);

    // Tensor-core banded attention
    attn_kernel<<<dim3(32, 32), 128, ATT_SMEM_BYTES>>>(bias);

    // Output projection
    bf16_gemm_kernel<1024, false><<<dim3(8, 32), 128, GEMM_SMEM_BYTES>>>(
        ath, atl, woh, wol, out);
}

// round 11
// speedup vs baseline: 1.1381x; 1.1381x over previous
#include <cuda_runtime.h>
#include <cuda_bf16.h>
#include <math.h>
#include <stdint.h>

#define BATCH 2
#define S_LEN 2048
#define D_MODEL 1024
#define NHEAD 16
#define DHEAD 64
#define NEGBIG -1e30f

// fp32 scratch (V only)
__device__ float g_v[BATCH*NHEAD*S_LEN*DHEAD];

// bf16 hi/lo planes
__device__ __nv_bfloat16 g_qh[BATCH*NHEAD*S_LEN*DHEAD], g_ql[BATCH*NHEAD*S_LEN*DHEAD];
__device__ __nv_bfloat16 g_kh[BATCH*NHEAD*S_LEN*DHEAD], g_kl[BATCH*NHEAD*S_LEN*DHEAD];
__device__ __nv_bfloat16 g_xh[4096*1024],  g_xl[4096*1024];
__device__ __nv_bfloat16 g_ath[4096*1024], g_atl[4096*1024];   // attention out planes
__device__ __nv_bfloat16 g_wqh[3072*1024], g_wql[3072*1024];   // transposed N x K
__device__ __nv_bfloat16 g_woh[1024*1024], g_wol[1024*1024];   // transposed N x K

__device__ __forceinline__ void bf16split(float x, __nv_bfloat16& hi, __nv_bfloat16& lo) {
    hi = __float2bfloat16_rn(x);
    lo = __float2bfloat16_rn(x - __bfloat162float(hi));
}
__device__ __forceinline__ uint32_t packbf(float a, float b) {
    __nv_bfloat162 v(__float2bfloat16_rn(a), __float2bfloat16_rn(b));
    return *reinterpret_cast<uint32_t*>(&v);
}
__device__ __forceinline__ uint32_t packlo(float a, float b, uint32_t hi) {
    __nv_bfloat162 h = *reinterpret_cast<__nv_bfloat162*>(&hi);
    __nv_bfloat162 v(__float2bfloat16_rn(a - __bfloat162float(h.x)),
                     __float2bfloat16_rn(b - __bfloat162float(h.y)));
    return *reinterpret_cast<uint32_t*>(&v);
}

// ---------------------------------------------------------------------------
// Pre-pass 1: elementwise split
// ---------------------------------------------------------------------------
__global__ void split_plain_kernel(const float* __restrict__ in,
                                   __nv_bfloat16* __restrict__ hi,
                                   __nv_bfloat16* __restrict__ lo)
{
    int i = (blockIdx.x * 256 + threadIdx.x) * 4;
    float4 v = *reinterpret_cast<const float4*>(in + i);
    __nv_bfloat16 h0,l0,h1,l1,h2,l2,h3,l3;
    bf16split(v.x,h0,l0); bf16split(v.y,h1,l1);
    bf16split(v.z,h2,l2); bf16split(v.w,h3,l3);
    *reinterpret_cast<__nv_bfloat162*>(hi + i)     = __nv_bfloat162(h0,h1);
    *reinterpret_cast<__nv_bfloat162*>(hi + i + 2) = __nv_bfloat162(h2,h3);
    *reinterpret_cast<__nv_bfloat162*>(lo + i)     = __nv_bfloat162(l0,l1);
    *reinterpret_cast<__nv_bfloat162*>(lo + i + 2) = __nv_bfloat162(l2,l3);
}

// ---------------------------------------------------------------------------
// Pre-pass 2: split + transpose
// ---------------------------------------------------------------------------
__global__ void transpose_split_kernel(const float* __restrict__ in,
                                       __nv_bfloat16* __restrict__ hiT,
                                       __nv_bfloat16* __restrict__ loT,
                                       int R, int C)
{
    __shared__ float t[32][33];
    const int tx = threadIdx.x, ty = threadIdx.y;
    const int r0 = blockIdx.y * 32, c0 = blockIdx.x * 32;
    #pragma unroll
    for (int i = 0; i < 4; i++)
        t[ty + i*8][tx] = in[(long)(r0 + ty + i*8) * C + c0 + tx];
    __syncthreads();
    #pragma unroll
    for (int i = 0; i < 4; i++) {
        float v = t[tx][ty + i*8];
        __nv_bfloat16 h, l;
        bf16split(v, h, l);
        long o = (long)(c0 + ty + i*8) * R + r0 + tx;
        hiT[o] = h; loT[o] = l;
    }
}

// ---------------------------------------------------------------------------
// GEMM: CTA 128x128, 4 warps, 64x64 warp tiles (R8 mainloop).
// QKV epilogue writes Q/K as bf16 hi/lo planes, V as fp32.
// ---------------------------------------------------------------------------
#define KP 40
#define GPLANE (128*KP)
#define GEMM_SMEM_BYTES (8 * GPLANE * (int)sizeof(__nv_bfloat16))

__device__ __forceinline__ void cpasync16(__nv_bfloat16* smem, const __nv_bfloat16* g) {
    uint32_t s = (uint32_t)__cvta_generic_to_shared(smem);
    asm volatile("cp.async.cg.shared.global [%0], [%1], 16;\n" :: "r"(s), "l"(g));
}

__device__ __forceinline__ void mma_bf16(float* c, const uint32_t* a, const uint32_t* b) {
    asm volatile(
        "mma.sync.aligned.m16n8k16.row.col.f32.bf16.bf16.f32 "
        "{%0,%1,%2,%3}, {%4,%5,%6,%7}, {%8,%9}, {%0,%1,%2,%3};"
        : "+f"(c[0]), "+f"(c[1]), "+f"(c[2]), "+f"(c[3])
        : "r"(a[0]), "r"(a[1]), "r"(a[2]), "r"(a[3]), "r"(b[0]), "r"(b[1]));
}

__device__ __forceinline__ void ldsm_x4(uint32_t* r, uint32_t addr) {
    asm volatile("ldmatrix.sync.aligned.m8n8.x4.shared.b16 {%0,%1,%2,%3}, [%4];"
                 : "=r"(r[0]), "=r"(r[1]), "=r"(r[2]), "=r"(r[3]) : "r"(addr));
}

template<int N, bool IS_QKV>
__global__ __launch_bounds__(128, 2)
void bf16_gemm_kernel(const __nv_bfloat16* __restrict__ Ahg,
                      const __nv_bfloat16* __restrict__ Alg,
                      const __nv_bfloat16* __restrict__ Bhg,
                      const __nv_bfloat16* __restrict__ Blg,
                      float* __restrict__ Out)
{
    extern __shared__ __nv_bfloat16 smg[];
    __nv_bfloat16* Ah = smg;
    __nv_bfloat16* Al = smg + 2*GPLANE;
    __nv_bfloat16* Bh = smg + 4*GPLANE;
    __nv_bfloat16* Bl = smg + 6*GPLANE;

    const int K = 1024;
    const int tid  = threadIdx.x;
    const int lane = tid & 31;
    const int wid  = tid >> 5;
    const int wm   = wid & 1;
    const int wn   = wid >> 1;
    const int m0 = blockIdx.y * 128;
    const int n0 = blockIdx.x * 128;

    const int lrow = ((lane >> 3) & 1) * 8 + (lane & 7);
    const int lkq  = (lane >> 4) * 8;
    const uint32_t lmo = (uint32_t)((lrow * KP + lkq) * 2);

    const uint32_t sAh = (uint32_t)__cvta_generic_to_shared(Ah);
    const uint32_t sAl = sAh + 2*GPLANE*2;
    const uint32_t sBh = sAh + 4*GPLANE*2;
    const uint32_t sBl = sAh + 6*GPLANE*2;

    float acc[4][8][4];
    #pragma unroll
    for (int mt = 0; mt < 4; mt++)
        #pragma unroll
        for (int nt = 0; nt < 8; nt++)
            #pragma unroll
            for (int i = 0; i < 4; i++) acc[mt][nt][i] = 0.f;

    auto load_tiles = [&](int k0, int buf) {
        #pragma unroll
        for (int u = 0; u < 4; u++) {
            int c = tid + u*128;
            int row = c >> 2, kc = (c & 3) * 8;
            long go = (long)(m0 + row)*K + k0 + kc;
            cpasync16(&Ah[buf*GPLANE + row*KP + kc], Ahg + go);
            cpasync16(&Al[buf*GPLANE + row*KP + kc], Alg + go);
        }
        #pragma unroll
        for (int u = 0; u < 4; u++) {
            int c = tid + u*128;
            int row = c >> 2, kc = (c & 3) * 8;
            long go = (long)(n0 + row)*K + k0 + kc;
            cpasync16(&Bh[buf*GPLANE + row*KP + kc], Bhg + go);
            cpasync16(&Bl[buf*GPLANE + row*KP + kc], Blg + go);
        }
        asm volatile("cp.async.commit_group;\n");
    };

    load_tiles(0, 0);

    const int NIT = K / 32;
    for (int it = 0; it < NIT; ++it) {
        const int buf = it & 1;
        asm volatile("cp.async.wait_group 0;\n");
        __syncthreads();
        if (it + 1 < NIT) load_tiles((it+1)*32, buf ^ 1);

        const uint32_t bofs = (uint32_t)(buf*GPLANE*2);

        #pragma unroll
        for (int ks = 0; ks < 2; ks++) {
            const uint32_t kbo = bofs + (uint32_t)(ks*16*2) + lmo;

            uint32_t ahf[4][4], alf[4][4];
            #pragma unroll
            for (int mt = 0; mt < 4; mt++) {
                uint32_t ro = (uint32_t)((wm*64 + mt*16) * KP * 2);
                ldsm_x4(ahf[mt], sAh + ro + kbo);
                ldsm_x4(alf[mt], sAl + ro + kbo);
            }
            uint32_t bhf[8][2], blf[8][2];
            #pragma unroll
            for (int p = 0; p < 4; p++) {
                uint32_t ro = (uint32_t)((wn*64 + p*16) * KP * 2);
                uint32_t r[4];
                ldsm_x4(r, sBh + ro + kbo);
                bhf[2*p+0][0] = r[0]; bhf[2*p+1][0] = r[1];
                bhf[2*p+0][1] = r[2]; bhf[2*p+1][1] = r[3];
                ldsm_x4(r, sBl + ro + kbo);
                blf[2*p+0][0] = r[0]; blf[2*p+1][0] = r[1];
                blf[2*p+0][1] = r[2]; blf[2*p+1][1] = r[3];
            }
            #pragma unroll
            for (int mt = 0; mt < 4; mt++)
                #pragma unroll
                for (int nt = 0; nt < 8; nt++) {
                    mma_bf16(acc[mt][nt], ahf[mt], blf[nt]);
                    mma_bf16(acc[mt][nt], alf[mt], bhf[nt]);
                    mma_bf16(acc[mt][nt], ahf[mt], bhf[nt]);
                }
        }
        __syncthreads();
    }

    #pragma unroll
    for (int mt = 0; mt < 4; mt++) {
        #pragma unroll
        for (int i = 0; i < 2; i++) {
            int row = m0 + wm*64 + mt*16 + (lane >> 2) + i*8;
            #pragma unroll
            for (int nt = 0; nt < 8; nt++) {
                int col = n0 + wn*64 + nt*8 + (lane & 3)*2;
                float2 v = make_float2(acc[mt][nt][i*2+0], acc[mt][nt][i*2+1]);
                if (IS_QKV) {
                    int b = row >> 11, s = row & 2047;
                    int which = col >> 10;
                    int h = (col >> 6) & 15;
                    int dh = col & 63;
                    long idx = (((long)(b*NHEAD + h))*S_LEN + s)*DHEAD + dh;
                    if (which == 2) {
                        *reinterpret_cast<float2*>(&g_v[idx]) = v;
                    } else {
                        uint32_t hp = packbf(v.x, v.y);
                        uint32_t lp = packlo(v.x, v.y, hp);
                        __nv_bfloat16* dh_ = (which == 0) ? g_qh : g_kh;
                        __nv_bfloat16* dl_ = (which == 0) ? g_ql : g_kl;
                        *reinterpret_cast<uint32_t*>(&dh_[idx]) = hp;
                        *reinterpret_cast<uint32_t*>(&dl_[idx]) = lp;
                    }
                } else {
                    *reinterpret_cast<float2*>(&Out[(long)row*N + col]) = v;
                }
            }
        }
    }
}

// ---------------------------------------------------------------------------
// Tensor-core banded attention, v2.
// Q/K staged via cp.async from precomputed bf16 planes; V (fp32) split +
// transposed into smem AFTER QK^T, overlaying the dead Q/K region.
// smem 72KB -> 2 CTAs/SM.
// ---------------------------------------------------------------------------
#define QP_ 72
#define KPP 72
#define VP_ 200
#define AQ_OFF 0
#define AQL_OFF (64*QP_)
#define AK_OFF (2*64*QP_)
#define AKL_OFF (AK_OFF + 192*KPP)
#define ATT_SMEM_ELEMS (AK_OFF + 2*192*KPP)   // 36864 elems = 72KB
#define ATT_SMEM_BYTES (ATT_SMEM_ELEMS * 2)
#define AV_OFF 0
#define AVL_OFF (64*VP_)                       // V planes overlay Q/K region

__global__ __launch_bounds__(128, 2)
void attn_kernel(const float* __restrict__ bias)
{
    extern __shared__ __nv_bfloat16 smb[];
    const int tid = threadIdx.x;
    const int lane = tid & 31;
    const int wid = tid >> 5;
    const int qt = blockIdx.x;
    const int bh = blockIdx.y;
    const int qstart = qt * 64;
    const int jbase = qstart - 128;

    const long bho = (long)bh * S_LEN * DHEAD;
    const __nv_bfloat16* qhg = g_qh + bho;
    const __nv_bfloat16* qlg = g_ql + bho;
    const __nv_bfloat16* khg = g_kh + bho;
    const __nv_bfloat16* klg = g_kl + bho;
    const float* vg = g_v + bho;

    // ---- stage Q/K planes via cp.async ----
    for (int t = tid; t < 512; t += 128) {           // Q: 64 rows x 8 chunks
        int row = t >> 3, c = (t & 7) * 8;
        long go = (long)(qstart + row)*DHEAD + c;
        cpasync16(&smb[AQ_OFF + row*QP_ + c], qhg + go);
        cpasync16(&smb[AQL_OFF + row*QP_ + c], qlg + go);
    }
    for (int t = tid; t < 1536; t += 128) {          // K: 192 rows x 8 chunks
        int row = t >> 3, c = (t & 7) * 8;
        int j = jbase + row;
        if (j >= 0) {
            long go = (long)j*DHEAD + c;
            cpasync16(&smb[AK_OFF + row*KPP + c], khg + go);
            cpasync16(&smb[AKL_OFF + row*KPP + c], klg + go);
        } else {
            uint4 z = make_uint4(0,0,0,0);
            *reinterpret_cast<uint4*>(&smb[AK_OFF + row*KPP + c]) = z;
            *reinterpret_cast<uint4*>(&smb[AKL_OFF + row*KPP + c]) = z;
        }
    }
    asm volatile("cp.async.commit_group;\n" ::: "memory");
    asm volatile("cp.async.wait_group 0;\n" ::: "memory");
    __syncthreads();

    const uint32_t sb = (uint32_t)__cvta_generic_to_shared(smb);
    const int lrow = ((lane >> 3) & 1) * 8 + (lane & 7);
    const int lkq  = (lane >> 4) * 8;
    const uint32_t lmoQ = (uint32_t)((lrow * QP_ + lkq) * 2);
    const uint32_t lmoK = (uint32_t)((lrow * KPP + lkq) * 2);
    const uint32_t lmoV = (uint32_t)((lrow * VP_ + lkq) * 2);

    // ---- QK^T: S (16 x 192 per warp) ----
    float S[24][4];
    #pragma unroll
    for (int nt = 0; nt < 24; nt++)
        #pragma unroll
        for (int i = 0; i < 4; i++) S[nt][i] = 0.f;

    #pragma unroll
    for (int ks = 0; ks < 4; ks++) {
        const uint32_t kb = (uint32_t)(ks*16*2);
        uint32_t qh[4], ql[4];
        ldsm_x4(qh, sb + (uint32_t)(AQ_OFF*2)  + (uint32_t)(wid*16*QP_*2) + kb + lmoQ);
        ldsm_x4(ql, sb + (uint32_t)(AQL_OFF*2) + (uint32_t)(wid*16*QP_*2) + kb + lmoQ);
        #pragma unroll
        for (int p = 0; p < 12; p++) {
            uint32_t r[4], bhh[2][2], bll[2][2];
            ldsm_x4(r, sb + (uint32_t)(AK_OFF*2) + (uint32_t)(p*16*KPP*2) + kb + lmoK);
            bhh[0][0]=r[0]; bhh[1][0]=r[1]; bhh[0][1]=r[2]; bhh[1][1]=r[3];
            ldsm_x4(r, sb + (uint32_t)(AKL_OFF*2) + (uint32_t)(p*16*KPP*2) + kb + lmoK);
            bll[0][0]=r[0]; bll[1][0]=r[1]; bll[0][1]=r[2]; bll[1][1]=r[3];
            #pragma unroll
            for (int q2 = 0; q2 < 2; q2++) {
                mma_bf16(S[2*p+q2], qh, bll[q2]);
                mma_bf16(S[2*p+q2], ql, bhh[q2]);
                mma_bf16(S[2*p+q2], qh, bhh[q2]);
            }
        }
    }
    __syncthreads();   // Q/K reads done; V may overlay

    // ---- stage V (split + transposed) into overlay region ----
    for (int t = tid; t < 192*64; t += 128) {
        int r = t >> 6, dh = t & 63;
        int j = jbase + r;
        float vv = (j >= 0) ? vg[(long)j*DHEAD + dh] : 0.f;
        __nv_bfloat16 h, l;
        bf16split(vv, h, l);
        smb[AV_OFF + dh*VP_ + r] = h;
        smb[AVL_OFF + dh*VP_ + r] = l;
    }

    // ---- bias + masks + softmax (registers; overlaps V store drain) ----
    const int row0 = wid*16 + (lane >> 2);
    const int gi0 = qstart + row0;
    const int gi1 = gi0 + 8;
    const float* bb = bias + (long)bh * S_LEN * S_LEN;
    const float scale = 0.125f;

    float m0 = NEGBIG, m1 = NEGBIG;
    #pragma unroll
    for (int nt = 0; nt < 24; nt++) {
        int cj = nt*8 + (lane & 3)*2;
        int gj = jbase + cj;
        int cg = (gj >= 0) ? gj : 0;
        float2 b0 = *reinterpret_cast<const float2*>(&bb[(long)gi0*S_LEN + cg]);
        float2 b1 = *reinterpret_cast<const float2*>(&bb[(long)gi1*S_LEN + cg]);
        bool v00 = (gj >= 0)   && (gj   <= gi0) && (gi0 - gj   <= 128);
        bool v01 = (gj+1 >= 0) && (gj+1 <= gi0) && (gi0 - gj-1 <= 128);
        bool v10 = (gj >= 0)   && (gj   <= gi1) && (gi1 - gj   <= 128);
        bool v11 = (gj+1 >= 0) && (gj+1 <= gi1) && (gi1 - gj-1 <= 128);
        S[nt][0] = v00 ? S[nt][0]*scale + b0.x : NEGBIG;
        S[nt][1] = v01 ? S[nt][1]*scale + b0.y : NEGBIG;
        S[nt][2] = v10 ? S[nt][2]*scale + b1.x : NEGBIG;
        S[nt][3] = v11 ? S[nt][3]*scale + b1.y : NEGBIG;
        m0 = fmaxf(m0, fmaxf(S[nt][0], S[nt][1]));
        m1 = fmaxf(m1, fmaxf(S[nt][2], S[nt][3]));
    }
    #pragma unroll
    for (int o = 1; o <= 2; o <<= 1) {
        m0 = fmaxf(m0, __shfl_xor_sync(0xffffffffu, m0, o));
        m1 = fmaxf(m1, __shfl_xor_sync(0xffffffffu, m1, o));
    }
    float s0 = 0.f, s1 = 0.f;
    #pragma unroll
    for (int nt = 0; nt < 24; nt++) {
        S[nt][0] = __expf(S[nt][0] - m0);
        S[nt][1] = __expf(S[nt][1] - m0);
        S[nt][2] = __expf(S[nt][2] - m1);
        S[nt][3] = __expf(S[nt][3] - m1);
        s0 += S[nt][0] + S[nt][1];
        s1 += S[nt][2] + S[nt][3];
    }
    #pragma unroll
    for (int o = 1; o <= 2; o <<= 1) {
        s0 += __shfl_xor_sync(0xffffffffu, s0, o);
        s1 += __shfl_xor_sync(0xffffffffu, s1, o);
    }
    const float i0 = 1.f / s0, i1 = 1.f / s1;
    #pragma unroll
    for (int nt = 0; nt < 24; nt++) {
        S[nt][0] *= i0; S[nt][1] *= i0;
        S[nt][2] *= i1; S[nt][3] *= i1;
    }
    __syncthreads();   // V fully staged before PV

    // ---- PV: O (16 x 64 per warp), P from S regs ----
    float O[8][4];
    #pragma unroll
    for (int nt = 0; nt < 8; nt++)
        #pragma unroll
        for (int i = 0; i < 4; i++) O[nt][i] = 0.f;

    #pragma unroll
    for (int ks = 0; ks < 12; ks++) {
        uint32_t ah[4], al[4];
        ah[0] = packbf(S[2*ks][0],   S[2*ks][1]);
        ah[1] = packbf(S[2*ks][2],   S[2*ks][3]);
        ah[2] = packbf(S[2*ks+1][0], S[2*ks+1][1]);
        ah[3] = packbf(S[2*ks+1][2], S[2*ks+1][3]);
        al[0] = packlo(S[2*ks][0],   S[2*ks][1],   ah[0]);
        al[1] = packlo(S[2*ks][2],   S[2*ks][3],   ah[1]);
        al[2] = packlo(S[2*ks+1][0], S[2*ks+1][1], ah[2]);
        al[3] = packlo(S[2*ks+1][2], S[2*ks+1][3], ah[3]);

        const uint32_t kb = (uint32_t)(ks*16*2);
        #pragma unroll
        for (int p = 0; p < 4; p++) {
            uint32_t r[4], bhh[2][2], bll[2][2];
            ldsm_x4(r, sb + (uint32_t)(AV_OFF*2) + (uint32_t)(p*16*VP_*2) + kb + lmoV);
            bhh[0][0]=r[0]; bhh[1][0]=r[1]; bhh[0][1]=r[2]; bhh[1][1]=r[3];
            ldsm_x4(r, sb + (uint32_t)(AVL_OFF*2) + (uint32_t)(p*16*VP_*2) + kb + lmoV);
            bll[0][0]=r[0]; bll[1][0]=r[1]; bll[0][1]=r[2]; bll[1][1]=r[3];
            #pragma unroll
            for (int q2 = 0; q2 < 2; q2++) {
                mma_bf16(O[2*p+q2], ah, bll[q2]);
                mma_bf16(O[2*p+q2], al, bhh[q2]);
                mma_bf16(O[2*p+q2], ah, bhh[q2]);
            }
        }
    }

    // ---- epilogue: write attention-output bf16 planes ----
    const int b = bh >> 4, h = bh & 15;
    #pragma unroll
    for (int nt = 0; nt < 8; nt++) {
        int col = nt*8 + (lane & 3)*2;
        long o0 = ((long)(b*S_LEN + gi0))*D_MODEL + h*DHEAD + col;
        long o1 = ((long)(b*S_LEN + gi1))*D_MODEL + h*DHEAD + col;
        uint32_t h0 = packbf(O[nt][0], O[nt][1]);
        uint32_t l0 = packlo(O[nt][0], O[nt][1], h0);
        uint32_t h1 = packbf(O[nt][2], O[nt][3]);
        uint32_t l1 = packlo(O[nt][2], O[nt][3], h1);
        *reinterpret_cast<uint32_t*>(&g_ath[o0]) = h0;
        *reinterpret_cast<uint32_t*>(&g_atl[o0]) = l0;
        *reinterpret_cast<uint32_t*>(&g_ath[o1]) = h1;
        *reinterpret_cast<uint32_t*>(&g_atl[o1]) = l1;
    }
}

// ---------------------------------------------------------------------------
extern "C" void kernel_launch(void* const* d_in, const int* in_sizes, int n_in,
                              void* d_out, int out_size)
{
    const float* x    = (const float*)d_in[0];
    const float* bias = (const float*)d_in[1];
    // d_in[2] = causal mask (recomputed analytically in-kernel)
    const float* Wqkv = (const float*)d_in[3];
    const float* Wout = (const float*)d_in[4];
    float* out = (float*)d_out;

    __nv_bfloat16 *xh, *xl, *ath, *atl, *wqh, *wql, *woh, *wol;
    cudaGetSymbolAddress((void**)&xh,  g_xh);  cudaGetSymbolAddress((void**)&xl,  g_xl);
    cudaGetSymbolAddress((void**)&ath, g_ath); cudaGetSymbolAddress((void**)&atl, g_atl);
    cudaGetSymbolAddress((void**)&wqh, g_wqh); cudaGetSymbolAddress((void**)&wql, g_wql);
    cudaGetSymbolAddress((void**)&woh, g_woh); cudaGetSymbolAddress((void**)&wol, g_wol);

    cudaFuncSetAttribute(bf16_gemm_kernel<3072, true>,
                         cudaFuncAttributeMaxDynamicSharedMemorySize, GEMM_SMEM_BYTES);
    cudaFuncSetAttribute(bf16_gemm_kernel<1024, false>,
                         cudaFuncAttributeMaxDynamicSharedMemorySize, GEMM_SMEM_BYTES);
    cudaFuncSetAttribute(attn_kernel,
                         cudaFuncAttributeMaxDynamicSharedMemorySize, ATT_SMEM_BYTES);

    // Pre-passes
    split_plain_kernel<<<4096, 256>>>(x, xh, xl);
    transpose_split_kernel<<<dim3(3072/32, 1024/32), dim3(32, 8)>>>(Wqkv, wqh, wql, 1024, 3072);
    transpose_split_kernel<<<dim3(1024/32, 1024/32), dim3(32, 8)>>>(Wout, woh, wol, 1024, 1024);

    // QKV projection
    bf16_gemm_kernel<3072, true><<<dim3(24, 32), 128, GEMM_SMEM_BYTES>>>(
        xh, xl, wqh, wql, nullptr);

    // Tensor-core banded attention
    attn_kernel<<<dim3(32, 32), 128, ATT_SMEM_BYTES>>>(bias);

    // Output projection
    bf16_gemm_kernel<1024, false><<<dim3(8, 32), 128, GEMM_SMEM_BYTES>>>(
        ath, atl, woh, wol, out);
}